// round 11
// baseline (speedup 1.0000x reference)
#include <cuda_runtime.h>
#include <cstdint>

// ---------------------------------------------------------------------------
// PureCartesianTensorProductO3.
// R9: 512 threads = 2 s_out-groups x 2 m-half subgroups x 128.
//  - s_out groups: g0 handles ss{0,3}, g1 ss{1,2} (disjoint output parity)
//  - m-halves: [0,MH) / [MH,MT), MH=ceil(MT/2): accs halve -> ~110 regs,
//    4 warps/SMSP at unchanged smem (186KB) and unchanged wavefront totals.
// Path groups merged by (L1,L2) as R8. CHUNK=1 (KSLOTS=32).
// ---------------------------------------------------------------------------

#define NROWS   8192
#define FEAT    832
#define SBLK    416
#define TILE    16
#define NTHREADS 512
#define KSLOTS  32

// path tables (compile-time)
__host__ __device__ constexpr int kP3[3]   = {1, 3, 9};
__host__ __device__ constexpr int kLOFF[3] = {0, 32, 128};
__host__ __device__ constexpr int kL1[15] = {0,0,0,1,1,1,1,1,1,2,2,2,2,2,2};
__host__ __device__ constexpr int kL2[15] = {0,1,2,0,1,1,1,2,2,0,1,1,2,2,2};
__host__ __device__ constexpr int kLO[15] = {0,1,2,1,2,0,1,1,2,2,1,2,2,0,1};
__host__ __device__ constexpr int kUE[15] = {0,0,0,0,0,0,1,0,1,0,0,1,0,0,1};

// SMEM carve (floats) — identical totals to R8
#define SX_STRIDE 832
#define SX_FLOATS (TILE * SX_STRIDE)           // 13312
#define SB_G      (13 * 512)                   // 6656 per s_out group
#define SW_G      (3 * 1088)                   // 3264 per s_out group
#define SMEM_FLOATS (2 * SX_FLOATS + 2 * SB_G + 2 * SW_G)   // 46464
#define SMEM_BYTES (SMEM_FLOATS * 4)           // 185856 B

typedef unsigned long long u64;

__device__ __forceinline__ u64 pk2(float x, float y) {
    u64 r; asm("mov.b64 %0, {%1, %2};" : "=l"(r) : "f"(x), "f"(y)); return r;
}
__device__ __forceinline__ void upk2(u64 v, float& x, float& y) {
    asm("mov.b64 {%0, %1}, %2;" : "=f"(x), "=f"(y) : "l"(v));
}
// packed 2x fp32 FMA (PTX-only on sm_103a)
__device__ __forceinline__ void ffma2(u64& d, u64 a, u64 b) {
    asm("fma.rn.f32x2 %0, %1, %2, %0;" : "+l"(d) : "l"(a), "l"(b));
}

__device__ __forceinline__ float dot3(const float* __restrict__ u, const float* __restrict__ v) {
    return fmaf(u[0], v[0], fmaf(u[1], v[1], u[2] * v[2]));
}
__device__ __forceinline__ void cross3(const float* __restrict__ u, const float* __restrict__ v,
                                       float* __restrict__ o) {
    o[0] = u[1] * v[2] - u[2] * v[1];
    o[1] = u[2] * v[0] - u[0] * v[2];
    o[2] = u[0] * v[1] - u[1] * v[0];
}

// Spatial contraction per path (verified against _path_eq; unchanged since R1 fix)
template <int P>
__device__ __forceinline__ void compute_B(const float* __restrict__ t1,
                                          const float* __restrict__ t2,
                                          float* __restrict__ B) {
    if constexpr (P == 0) {
        B[0] = t1[0] * t2[0];
    } else if constexpr (P == 1) {
        #pragma unroll
        for (int m = 0; m < 3; ++m) B[m] = t1[0] * t2[m];
    } else if constexpr (P == 2) {
        #pragma unroll
        for (int m = 0; m < 9; ++m) B[m] = t1[0] * t2[m];
    } else if constexpr (P == 3) {
        #pragma unroll
        for (int m = 0; m < 3; ++m) B[m] = t1[m] * t2[0];
    } else if constexpr (P == 4) {
        #pragma unroll
        for (int i = 0; i < 3; ++i)
            #pragma unroll
            for (int j = 0; j < 3; ++j) B[3 * i + j] = t1[i] * t2[j];
    } else if constexpr (P == 5) {
        B[0] = dot3(t1, t2);
    } else if constexpr (P == 6) {
        cross3(t1, t2, B);
    } else if constexpr (P == 7) {
        #pragma unroll
        for (int d = 0; d < 3; ++d) B[d] = dot3(t1, t2 + 3 * d);
    } else if constexpr (P == 8) {
        #pragma unroll
        for (int d = 0; d < 3; ++d) cross3(t1, t2 + 3 * d, B + 3 * d);
    } else if constexpr (P == 9) {
        #pragma unroll
        for (int m = 0; m < 9; ++m) B[m] = t1[m] * t2[0];
    } else if constexpr (P == 10) {
        #pragma unroll
        for (int c = 0; c < 3; ++c) B[c] = dot3(t1 + 3 * c, t2);
    } else if constexpr (P == 11) {
        #pragma unroll
        for (int c = 0; c < 3; ++c) cross3(t1 + 3 * c, t2, B + 3 * c);
    } else if constexpr (P == 12) {
        #pragma unroll
        for (int c = 0; c < 3; ++c)
            #pragma unroll
            for (int e = 0; e < 3; ++e) B[3 * c + e] = dot3(t1 + 3 * c, t2 + 3 * e);
    } else if constexpr (P == 13) {
        float s = 0.f;
        #pragma unroll
        for (int i = 0; i < 9; ++i) s = fmaf(t1[i], t2[i], s);
        B[0] = s;
    } else {  // P==14
        float M01 = dot3(t1 + 0, t2 + 3), M02 = dot3(t1 + 0, t2 + 6);
        float M10 = dot3(t1 + 3, t2 + 0), M12 = dot3(t1 + 3, t2 + 6);
        float M20 = dot3(t1 + 6, t2 + 0), M21 = dot3(t1 + 6, t2 + 3);
        B[0] = M12 - M21;
        B[1] = M20 - M02;
        B[2] = M01 - M10;
    }
}

// GEMM chunk over m in [MLO, MHI); W loads pruned at compile time to the
// paths that range actually touches.
template <int MA, int MB, int NP, int MLO, int MHI>
__device__ __forceinline__ void gemm_chunk(u64* __restrict__ acc0, u64* __restrict__ acc1,
                                           const float* __restrict__ sB,
                                           const float* __restrict__ sW,
                                           int zp, int rp) {
    #pragma unroll 2
    for (int kk = 0; kk < KSLOTS / 2; ++kk) {
        u64 wA0[NP], wB0[NP], wA1[NP], wB1[NP];
        #pragma unroll
        for (int p = 0; p < NP; ++p) {
            const int plo = (p == 0) ? 0 : ((p == 1) ? MA : MA + MB);
            const int phi = (p == 0) ? MA : ((p == 1) ? MA + MB : 999);
            if (phi > MLO && plo < MHI) {   // compile-time prune
                float2 wa = *reinterpret_cast<const float2*>(
                    sW + p * 1088 + (2 * kk) * 34 + 2 * zp);
                float2 wc = *reinterpret_cast<const float2*>(
                    sW + p * 1088 + (2 * kk + 1) * 34 + 2 * zp);
                wA0[p] = pk2(wa.x, wa.x);
                wB0[p] = pk2(wa.y, wa.y);
                wA1[p] = pk2(wc.x, wc.x);
                wB1[p] = pk2(wc.y, wc.y);
            }
        }
        const float* bp = sB + rp * 64 + 4 * kk;
        #pragma unroll
        for (int m = MLO; m < MHI; ++m) {
            const int p = (m < MA) ? 0 : ((m < MA + MB) ? 1 : 2);
            ulonglong2 q = *reinterpret_cast<const ulonglong2*>(bp + m * 512);
            ffma2(acc0[m - MLO], wA0[p], q.x);
            ffma2(acc1[m - MLO], wB0[p], q.x);
            ffma2(acc0[m - MLO], wA1[p], q.y);
            ffma2(acc1[m - MLO], wB1[p], q.y);
        }
    }
}

template <int PA, int PB, int PC, int MLO, int MHI>
__device__ __forceinline__ void flush_range(const u64* __restrict__ acc0,
                                            const u64* __restrict__ acc1,
                                            float* __restrict__ out,
                                            int row0, int zp, int rp, int sgroup) {
    constexpr int MA = kP3[kLO[PA]];
    constexpr int MB = (PB >= 0) ? kP3[kLO[PB >= 0 ? PB : 0]] : 0;
    float* o0 = out + (size_t)(row0 + 2 * rp) * FEAT;
    float* o1 = o0 + FEAT;
    #pragma unroll
    for (int m = MLO; m < MHI; ++m) {
        const int p   = (m < MA) ? 0 : ((m < MA + MB) ? 1 : 2);
        const int P   = (p == 0) ? PA : ((p == 1) ? PB : PC);
        const int Lo  = kLO[P], UE = kUE[P];
        const int Mo  = kP3[Lo], Oo = kLOFF[Lo];
        const int mm  = m - ((p == 0) ? 0 : ((p == 1) ? MA : MA + MB));
        const int s_out = (sgroup == 0) ? UE : (1 ^ UE);
        const int ob  = s_out * SBLK + Oo;
        float v00, v01, v10, v11;
        upk2(acc0[m - MLO], v00, v01);
        upk2(acc1[m - MLO], v10, v11);
        o0[ob + (2 * zp) * Mo + mm]     += v00;
        o1[ob + (2 * zp) * Mo + mm]     += v01;
        o0[ob + (2 * zp + 1) * Mo + mm] += v10;
        o1[ob + (2 * zp + 1) * Mo + mm] += v11;
    }
}

// Merged processing for up to 3 paths sharing (L1,L2). PB/PC = -1 if absent.
template <int PA, int PB, int PC>
__device__ __forceinline__ void process_group(const float* __restrict__ wgt,
                                              float* __restrict__ out,
                                              const float* __restrict__ sx1,
                                              const float* __restrict__ sx2,
                                              float* __restrict__ sB,
                                              float* __restrict__ sW,
                                              int row0, int gtid, int sgroup) {
    constexpr int NP = 1 + (PB >= 0 ? 1 : 0) + (PC >= 0 ? 1 : 0);
    constexpr int L1 = kL1[PA], L2 = kL2[PA];
    constexpr int d1 = kP3[L1], d2 = kP3[L2];
    constexpr int O1 = kLOFF[L1], O2 = kLOFF[L2];
    constexpr int MA = kP3[kLO[PA]];
    constexpr int MB = (PB >= 0) ? kP3[kLO[PB >= 0 ? PB : 0]] : 0;
    constexpr int MC = (PC >= 0) ? kP3[kLO[PC >= 0 ? PC : 0]] : 0;
    constexpr int MT = MA + MB + MC;
    constexpr int MH = (MT + 1) / 2;   // split point; subgroup0 [0,MH), subgroup1 [MH,MT)

    const int mh   = gtid >> 7;        // m-half subgroup (warp-uniform)
    const int wtid = gtid & 127;
    const int zp = wtid & 15;          // Z-pair
    const int rp = wtid >> 4;          // row-pair

    u64 acc0[MH], acc1[MH];
    #pragma unroll
    for (int m = 0; m < MH; ++m) { acc0[m] = 0ull; acc1[m] = 0ull; }

    #pragma unroll 1
    for (int ssi = 0; ssi < 2; ++ssi) {
        const int ss = (sgroup == 0) ? (ssi == 0 ? 0 : 3) : (ssi == 0 ? 1 : 2);
        const int s1 = ss >> 1, s2 = ss & 1;

        #pragma unroll 1
        for (int a0 = 0; a0 < 32; ++a0) {
            __syncthreads();  // prior GEMM done reading sB/sW (also orders x fill)
            // ---- stage W: NP x 32Z x 32k over 256 threads of this s_out group
            #pragma unroll
            for (int it = 0; it < NP * 4; ++it) {
                int i = gtid + it * 256;
                int p = i >> 10, z = (i >> 5) & 31, k = i & 31;
                int pidx = (p == 0) ? PA : ((p == 1) ? PB : PC);
                sW[p * 1088 + k * 34 + z] =
                    wgt[(size_t)(pidx * 4 + ss) * 32768 + z * 1024 + a0 * 32 + k];
            }
            // ---- stage B: 32k x 16r over 256 threads; one t1/t2 read -> all MT
            #pragma unroll
            for (int it = 0; it < 2; ++it) {
                int e = gtid + it * 256;
                int k = e & 31, r = e >> 5;
                const float* t1 = sx1 + r * SX_STRIDE + s1 * SBLK + O1 + a0 * d1;
                const float* t2 = sx2 + r * SX_STRIDE + s2 * SBLK + O2 + k * d2;
                float Bm[MT];
                compute_B<PA>(t1, t2, Bm);
                if constexpr (PB >= 0) compute_B<PB>(t1, t2, Bm + MA);
                if constexpr (PC >= 0) compute_B<PC>(t1, t2, Bm + MA + MB);
                float* d = sB + (r >> 1) * 64 + 2 * k + (r & 1);
                #pragma unroll
                for (int m = 0; m < MT; ++m) d[m * 512] = Bm[m];
            }
            __syncthreads();
            // ---- rank-32 update on this subgroup's m-range (no barriers inside)
            if (mh == 0) gemm_chunk<MA, MB, NP, 0, MH>(acc0, acc1, sB, sW, zp, rp);
            else         gemm_chunk<MA, MB, NP, MH, MT>(acc0, acc1, sB, sW, zp, rp);
        }
    }
    // ---- flush this subgroup's m-range (disjoint across mh / sgroup / CTA rows)
    if (mh == 0) flush_range<PA, PB, PC, 0, MH>(acc0, acc1, out, row0, zp, rp, sgroup);
    else         flush_range<PA, PB, PC, MH, MT>(acc0, acc1, out, row0, zp, rp, sgroup);
}

__global__ __launch_bounds__(NTHREADS, 1)
void tp_o3_kernel(const float* __restrict__ x1, const float* __restrict__ x2,
                  const float* __restrict__ wgt, float* __restrict__ out) {
    extern __shared__ float sm[];
    float* sx1 = sm;
    float* sx2 = sx1 + SX_FLOATS;
    float* sBb = sx2 + SX_FLOATS;
    float* sWb = sBb + 2 * SB_G;

    const int tid    = threadIdx.x;
    const int sgroup = tid >> 8;       // s_out group (0/1), 256 threads each
    const int gtid   = tid & 255;
    const int row0   = blockIdx.x * TILE;

    float* sB = sBb + sgroup * SB_G;
    float* sW = sWb + sgroup * SW_G;

    // stage input tiles (contiguous float4 copy)
    {
        const float4* g1 = reinterpret_cast<const float4*>(x1 + (size_t)row0 * FEAT);
        const float4* g2 = reinterpret_cast<const float4*>(x2 + (size_t)row0 * FEAT);
        float4* s1v = reinterpret_cast<float4*>(sx1);
        float4* s2v = reinterpret_cast<float4*>(sx2);
        #pragma unroll 4
        for (int i = tid; i < TILE * FEAT / 4; i += NTHREADS) {
            s1v[i] = g1[i];
            s2v[i] = g2[i];
        }
    }
    // (first __syncthreads inside each group's chunk loop orders the fill)

    process_group< 0, -1, -1>(wgt, out, sx1, sx2, sB, sW, row0, gtid, sgroup);  // (0,0)
    process_group< 1, -1, -1>(wgt, out, sx1, sx2, sB, sW, row0, gtid, sgroup);  // (0,1)
    process_group< 2, -1, -1>(wgt, out, sx1, sx2, sB, sW, row0, gtid, sgroup);  // (0,2)
    process_group< 3, -1, -1>(wgt, out, sx1, sx2, sB, sW, row0, gtid, sgroup);  // (1,0)
    process_group< 4,  5,  6>(wgt, out, sx1, sx2, sB, sW, row0, gtid, sgroup);  // (1,1)
    process_group< 7,  8, -1>(wgt, out, sx1, sx2, sB, sW, row0, gtid, sgroup);  // (1,2)
    process_group< 9, -1, -1>(wgt, out, sx1, sx2, sB, sW, row0, gtid, sgroup);  // (2,0)
    process_group<10, 11, -1>(wgt, out, sx1, sx2, sB, sW, row0, gtid, sgroup);  // (2,1)
    process_group<12, 13, 14>(wgt, out, sx1, sx2, sB, sW, row0, gtid, sgroup);  // (2,2)
}

extern "C" void kernel_launch(void* const* d_in, const int* in_sizes, int n_in,
                              void* d_out, int out_size) {
    const float* x1  = (const float*)d_in[0];
    const float* x2  = (const float*)d_in[1];
    const float* wgt = (const float*)d_in[2];
    float* out = (float*)d_out;

    cudaFuncSetAttribute(tp_o3_kernel, cudaFuncAttributeMaxDynamicSharedMemorySize, SMEM_BYTES);
    cudaMemsetAsync(d_out, 0, (size_t)out_size * sizeof(float), 0);
    tp_o3_kernel<<<NROWS / TILE, NTHREADS, SMEM_BYTES>>>(x1, x2, wgt, out);
}

// round 16
// speedup vs baseline: 1.5414x; 1.5414x over previous
#include <cuda_runtime.h>
#include <cstdint>

// ---------------------------------------------------------------------------
// PureCartesianTensorProductO3 — warp-level mma.sync TF32 version (R13).
// Per CTA (path, s_out-pair, n-tile): D[(n,m),Z] = sum_k Btensor*W, K=2048
// (2 ss of equal s_out), M=128 rows, N=32 Z. 3-term TF32 split for accuracy.
// mma.sync.m16n8k8.tf32 (portable sm_80+ PTX -> HMMA; no tcgen05 on this
// harness's plain-sm_103 ptxas target). Epilogue: atomicAdd scatter.
// ---------------------------------------------------------------------------

#define NROWS 8192
#define FEAT  832
#define SBLK  416
#define NTH   256

__host__ __device__ constexpr int kP3[3]   = {1, 3, 9};
__host__ __device__ constexpr int kLOFF[3] = {0, 32, 128};
__host__ __device__ constexpr int kL1[15] = {0,0,0,1,1,1,1,1,1,2,2,2,2,2,2};
__host__ __device__ constexpr int kL2[15] = {0,1,2,0,1,1,1,2,2,0,1,1,2,2,2};
__host__ __device__ constexpr int kLO[15] = {0,1,2,1,2,0,1,1,2,2,1,2,2,0,1};
__host__ __device__ constexpr int kUE[15] = {0,0,0,0,0,0,1,0,1,0,0,1,0,0,1};
// rows-per-tile n_sub = floor(128/Mout)
__host__ __device__ constexpr int kNS[15] = {128,42,14,42,14,128,42,42,14,14,42,14,14,128,42};
// CTA offsets: per path 2*ceil(8192/n_sub)
__host__ __device__ constexpr int kOFF[16] =
    {0,128,520,1692,2084,3256,3384,3776,4168,5340,6512,6904,8076,9248,9376,9768};
#define GRID_TOTAL 9768

// smem (floats): B hi/lo [128][36], W hi/lo [32][36]
#define BROW 36
#define SBH 0
#define SBL 4608
#define SWH 9216
#define SWL 10368
#define SMEM_FLOATS 11520   // 46080 B (static, under 48KB)

__device__ __forceinline__ uint32_t f2tf32(float x) {
    uint32_t r; asm("cvt.rna.tf32.f32 %0, %1;" : "=r"(r) : "f"(x)); return r;
}
__device__ __forceinline__ void mma8(float* c, uint32_t a0, uint32_t a1, uint32_t a2,
                                     uint32_t a3, uint32_t b0, uint32_t b1) {
    asm volatile(
        "mma.sync.aligned.m16n8k8.row.col.f32.tf32.tf32.f32 "
        "{%0,%1,%2,%3}, {%4,%5,%6,%7}, {%8,%9}, {%0,%1,%2,%3};"
        : "+f"(c[0]), "+f"(c[1]), "+f"(c[2]), "+f"(c[3])
        : "r"(a0), "r"(a1), "r"(a2), "r"(a3), "r"(b0), "r"(b1));
}

__device__ __forceinline__ float dot3(const float* u, const float* v) {
    return fmaf(u[0], v[0], fmaf(u[1], v[1], u[2] * v[2]));
}
__device__ __forceinline__ void cross3(const float* u, const float* v, float* o) {
    o[0] = u[1] * v[2] - u[2] * v[1];
    o[1] = u[2] * v[0] - u[0] * v[2];
    o[2] = u[0] * v[1] - u[1] * v[0];
}

// Spatial contraction per path (verified against _path_eq; unchanged since R1 fix)
template <int P>
__device__ __forceinline__ void compute_B(const float* t1, const float* t2, float* B) {
    if constexpr (P == 0) {
        B[0] = t1[0] * t2[0];
    } else if constexpr (P == 1) {
        #pragma unroll
        for (int m = 0; m < 3; ++m) B[m] = t1[0] * t2[m];
    } else if constexpr (P == 2) {
        #pragma unroll
        for (int m = 0; m < 9; ++m) B[m] = t1[0] * t2[m];
    } else if constexpr (P == 3) {
        #pragma unroll
        for (int m = 0; m < 3; ++m) B[m] = t1[m] * t2[0];
    } else if constexpr (P == 4) {
        #pragma unroll
        for (int i = 0; i < 3; ++i)
            #pragma unroll
            for (int j = 0; j < 3; ++j) B[3 * i + j] = t1[i] * t2[j];
    } else if constexpr (P == 5) {
        B[0] = dot3(t1, t2);
    } else if constexpr (P == 6) {
        cross3(t1, t2, B);
    } else if constexpr (P == 7) {
        #pragma unroll
        for (int d = 0; d < 3; ++d) B[d] = dot3(t1, t2 + 3 * d);
    } else if constexpr (P == 8) {
        #pragma unroll
        for (int d = 0; d < 3; ++d) cross3(t1, t2 + 3 * d, B + 3 * d);
    } else if constexpr (P == 9) {
        #pragma unroll
        for (int m = 0; m < 9; ++m) B[m] = t1[m] * t2[0];
    } else if constexpr (P == 10) {
        #pragma unroll
        for (int c = 0; c < 3; ++c) B[c] = dot3(t1 + 3 * c, t2);
    } else if constexpr (P == 11) {
        #pragma unroll
        for (int c = 0; c < 3; ++c) cross3(t1 + 3 * c, t2, B + 3 * c);
    } else if constexpr (P == 12) {
        #pragma unroll
        for (int c = 0; c < 3; ++c)
            #pragma unroll
            for (int e = 0; e < 3; ++e) B[3 * c + e] = dot3(t1 + 3 * c, t2 + 3 * e);
    } else if constexpr (P == 13) {
        float s = 0.f;
        #pragma unroll
        for (int i = 0; i < 9; ++i) s = fmaf(t1[i], t2[i], s);
        B[0] = s;
    } else {  // P==14
        float M01 = dot3(t1 + 0, t2 + 3), M02 = dot3(t1 + 0, t2 + 6);
        float M10 = dot3(t1 + 3, t2 + 0), M12 = dot3(t1 + 3, t2 + 6);
        float M20 = dot3(t1 + 6, t2 + 0), M21 = dot3(t1 + 6, t2 + 3);
        B[0] = M12 - M21;
        B[1] = M20 - M02;
        B[2] = M01 - M10;
    }
}

// split to tf32 hi/lo, store as float bit-patterns in smem
__device__ __forceinline__ void split_store(float* sh, float* sl, int idx, float x) {
    uint32_t hi = f2tf32(x);
    float lo = x - __uint_as_float(hi);
    sh[idx] = __uint_as_float(hi);
    sl[idx] = __uint_as_float(f2tf32(lo));
}

template <int P>
__device__ __noinline__ void proc_path(int rem,
                                       const float* __restrict__ x1,
                                       const float* __restrict__ x2,
                                       const float* __restrict__ wgt,
                                       float* __restrict__ out,
                                       float* smem) {
    constexpr int L1 = kL1[P], L2 = kL2[P], Lo = kLO[P], UE = kUE[P];
    constexpr int d1 = kP3[L1], d2 = kP3[L2], Mout = kP3[Lo];
    constexpr int O1 = kLOFF[L1], O2 = kLOFF[L2], Oo = kLOFF[Lo];
    constexpr int NSUB = kNS[P];
    constexpr int USED = NSUB * Mout;     // 126 or 128

    float* sBh = smem + SBH;
    float* sBl = smem + SBL;
    float* sWh = smem + SWH;
    float* sWl = smem + SWL;

    const int tid  = threadIdx.x;
    const int w    = tid >> 5;            // warp 0..7 -> rows w*16..w*16+15
    const int lane = tid & 31;
    const int grp  = lane >> 2;           // 0..7
    const int tig  = lane & 3;            // 0..3
    const int pair = rem & 1;
    const int tile = rem >> 1;
    const int n0   = tile * NSUB;
    const int s_out = (pair == 0) ? UE : (1 ^ UE);

    // zero pad rows once (never re-written by staging)
    if constexpr (USED < 128) {
        if (tid < (128 - USED) * 32) {
            int row = USED + (tid >> 5), k = tid & 31;
            sBh[row * BROW + k] = 0.f;
            sBl[row * BROW + k] = 0.f;
        }
    }

    float acc[4][4];
    #pragma unroll
    for (int zt = 0; zt < 4; ++zt)
        #pragma unroll
        for (int i = 0; i < 4; ++i) acc[zt][i] = 0.f;

    #pragma unroll 1
    for (int c = 0; c < 64; ++c) {
        const int ss = (pair == 0) ? ((c >= 32) ? 3 : 0) : ((c >= 32) ? 2 : 1);
        const int s1 = ss >> 1, s2 = ss & 1;
        const int a0 = c & 31;

        __syncthreads();   // prior MMA phase done reading smem (covers pad-zero too)

        // ---- stage W hi/lo: 32 Z x 32 k
        {
            const float* wb = wgt + ((size_t)(P * 4 + ss) << 15) + a0 * 32;
            #pragma unroll
            for (int it = 0; it < 4; ++it) {
                int t = tid + it * NTH;
                int z = t >> 5, k = t & 31;
                float wv = __ldg(wb + (size_t)z * 1024 + k);
                split_store(sWh, sWl, z * BROW + k, wv);
            }
        }
        // ---- stage B hi/lo: NSUB ln x 32 k, Mout rows each
        {
            const float* x1b = x1 + s1 * SBLK + O1 + a0 * d1;
            const float* x2b = x2 + s2 * SBLK + O2;
            constexpr int TOT = NSUB * 32;
            #pragma unroll 1
            for (int t = tid; t < TOT; t += NTH) {
                int ln = t >> 5, k = t & 31;
                int n = n0 + ln; if (n >= NROWS) n = NROWS - 1;
                float t1v[d1], t2v[d2], Bm[Mout];
                const float* p1 = x1b + (size_t)n * FEAT;
                const float* p2 = x2b + (size_t)n * FEAT + k * d2;
                #pragma unroll
                for (int i = 0; i < d1; ++i) t1v[i] = __ldg(p1 + i);
                #pragma unroll
                for (int j = 0; j < d2; ++j) t2v[j] = __ldg(p2 + j);
                compute_B<P>(t1v, t2v, Bm);
                #pragma unroll
                for (int m = 0; m < Mout; ++m)
                    split_store(sBh, sBl, (ln * Mout + m) * BROW + k, Bm[m]);
            }
        }
        __syncthreads();

        // ---- MMA phase: 4 k8 x 4 Z-tiles x 3 split terms
        const int r0 = w * 16 + grp;
        #pragma unroll
        for (int k8 = 0; k8 < 4; ++k8) {
            const int kb = k8 * 8 + tig;
            uint32_t ah0 = __float_as_uint(sBh[r0 * BROW + kb]);
            uint32_t ah1 = __float_as_uint(sBh[(r0 + 8) * BROW + kb]);
            uint32_t ah2 = __float_as_uint(sBh[r0 * BROW + kb + 4]);
            uint32_t ah3 = __float_as_uint(sBh[(r0 + 8) * BROW + kb + 4]);
            uint32_t al0 = __float_as_uint(sBl[r0 * BROW + kb]);
            uint32_t al1 = __float_as_uint(sBl[(r0 + 8) * BROW + kb]);
            uint32_t al2 = __float_as_uint(sBl[r0 * BROW + kb + 4]);
            uint32_t al3 = __float_as_uint(sBl[(r0 + 8) * BROW + kb + 4]);
            #pragma unroll
            for (int zt = 0; zt < 4; ++zt) {
                const int z = zt * 8 + grp;
                uint32_t bh0 = __float_as_uint(sWh[z * BROW + kb]);
                uint32_t bh1 = __float_as_uint(sWh[z * BROW + kb + 4]);
                uint32_t bl0 = __float_as_uint(sWl[z * BROW + kb]);
                uint32_t bl1 = __float_as_uint(sWl[z * BROW + kb + 4]);
                mma8(acc[zt], ah0, ah1, ah2, ah3, bh0, bh1);
                mma8(acc[zt], ah0, ah1, ah2, ah3, bl0, bl1);
                mma8(acc[zt], al0, al1, al2, al3, bh0, bh1);
            }
        }
    }

    // ---- epilogue: scatter-accumulate
    const int ob = s_out * SBLK + Oo;
    #pragma unroll
    for (int h = 0; h < 2; ++h) {
        const int row = w * 16 + grp + h * 8;
        bool ok = true;
        if constexpr (USED < 128) ok = (row < USED);
        int ln = row / Mout, m = row - ln * Mout;
        int n = n0 + ln;
        if (ok && n < NROWS) {
            float* op = out + (size_t)n * FEAT + ob + m;
            #pragma unroll
            for (int zt = 0; zt < 4; ++zt) {
                const int z = zt * 8 + 2 * tig;
                atomicAdd(op + (size_t)z * Mout, acc[zt][h * 2 + 0]);
                atomicAdd(op + (size_t)(z + 1) * Mout, acc[zt][h * 2 + 1]);
            }
        }
    }
}

__global__ __launch_bounds__(NTH)
void tp_mma_kernel(const float* __restrict__ x1, const float* __restrict__ x2,
                   const float* __restrict__ wgt, float* __restrict__ out) {
    __shared__ float smem[SMEM_FLOATS];
    const int bid = blockIdx.x;
    if      (bid < kOFF[1])  proc_path<0>(bid - kOFF[0], x1, x2, wgt, out, smem);
    else if (bid < kOFF[2])  proc_path<1>(bid - kOFF[1], x1, x2, wgt, out, smem);
    else if (bid < kOFF[3])  proc_path<2>(bid - kOFF[2], x1, x2, wgt, out, smem);
    else if (bid < kOFF[4])  proc_path<3>(bid - kOFF[3], x1, x2, wgt, out, smem);
    else if (bid < kOFF[5])  proc_path<4>(bid - kOFF[4], x1, x2, wgt, out, smem);
    else if (bid < kOFF[6])  proc_path<5>(bid - kOFF[5], x1, x2, wgt, out, smem);
    else if (bid < kOFF[7])  proc_path<6>(bid - kOFF[6], x1, x2, wgt, out, smem);
    else if (bid < kOFF[8])  proc_path<7>(bid - kOFF[7], x1, x2, wgt, out, smem);
    else if (bid < kOFF[9])  proc_path<8>(bid - kOFF[8], x1, x2, wgt, out, smem);
    else if (bid < kOFF[10]) proc_path<9>(bid - kOFF[9], x1, x2, wgt, out, smem);
    else if (bid < kOFF[11]) proc_path<10>(bid - kOFF[10], x1, x2, wgt, out, smem);
    else if (bid < kOFF[12]) proc_path<11>(bid - kOFF[11], x1, x2, wgt, out, smem);
    else if (bid < kOFF[13]) proc_path<12>(bid - kOFF[12], x1, x2, wgt, out, smem);
    else if (bid < kOFF[14]) proc_path<13>(bid - kOFF[13], x1, x2, wgt, out, smem);
    else                     proc_path<14>(bid - kOFF[14], x1, x2, wgt, out, smem);
}

extern "C" void kernel_launch(void* const* d_in, const int* in_sizes, int n_in,
                              void* d_out, int out_size) {
    const float* x1  = (const float*)d_in[0];
    const float* x2  = (const float*)d_in[1];
    const float* wgt = (const float*)d_in[2];
    float* out = (float*)d_out;

    cudaMemsetAsync(d_out, 0, (size_t)out_size * sizeof(float), 0);
    tp_mma_kernel<<<GRID_TOTAL, NTH>>>(x1, x2, wgt, out);
}